// round 11
// baseline (speedup 1.0000x reference)
#include <cuda_runtime.h>
#include <cuda_bf16.h>

#define THREADS 512
#define T_STEPS 20
#define BETA 0.9f
#define THR 1.0f

typedef unsigned int u32;

// ---- smem byte offsets (dedicated regions; folded phases) ----
#define SW1 0            // 3 x 128 x 32B
#define SW2 12288        // 3 x 128 x 256B
#define SW3 110592       // 3 x 64 x 256B
#define SW4 159744       // 3 x 16 x 128B
#define SS1 165888       // 64 x 256B
#define SS2 182272       // 64 x 256B
#define SS3 198656       // 64 x 128B
#define SXS 206848       // 3 x 64 x 32B
#define SM_TOTAL 212992

__device__ __forceinline__ float bfv(float v) { return __bfloat162float(__float2bfloat16(v)); }
__device__ __forceinline__ u32 bfb(float v) { return (u32)__bfloat16_as_ushort(__float2bfloat16(v)); }

__device__ __forceinline__ void ldsm4(u32 a[4], u32 addr) {
    asm volatile("ldmatrix.sync.aligned.m8n8.x4.shared.b16 {%0,%1,%2,%3}, [%4];"
        : "=r"(a[0]), "=r"(a[1]), "=r"(a[2]), "=r"(a[3]) : "r"(addr));
}
__device__ __forceinline__ void mma_bf16(float d[4], const u32 a[4], u32 b0, u32 b1) {
    asm volatile("mma.sync.aligned.m16n8k16.row.col.f32.bf16.bf16.f32 "
        "{%0,%1,%2,%3}, {%4,%5,%6,%7}, {%8,%9}, {%0,%1,%2,%3};"
        : "+f"(d[0]), "+f"(d[1]), "+f"(d[2]), "+f"(d[3])
        : "r"(a[0]), "r"(a[1]), "r"(a[2]), "r"(a[3]), "r"(b0), "r"(b1));
}
__device__ __forceinline__ void sts32(u32 addr, u32 v) {
    asm volatile("st.shared.b32 [%0], %1;" :: "r"(addr), "r"(v) : "memory");
}

__device__ __forceinline__ void lif4(float* mem, const float* d, u32 &p0, u32 &p1) {
    float s[4];
#pragma unroll
    for (int e = 0; e < 4; e++) {
        float m = mem[e];
        float reset = (m > THR) ? 1.0f : 0.0f;
        m = fmaf(BETA, m, d[e]) - reset;
        mem[e] = m;
        s[e] = (m > THR) ? 1.0f : 0.0f;
    }
    p0 = (s[0] != 0.0f ? 0x3F80u : 0u) | (s[1] != 0.0f ? 0x3F800000u : 0u);
    p1 = (s[2] != 0.0f ? 0x3F80u : 0u) | (s[3] != 0.0f ? 0x3F800000u : 0u);
}

__global__ void __launch_bounds__(THREADS, 1)
snn_mma_kernel(const float* __restrict__ x,
               const float* __restrict__ w1g,
               const float* __restrict__ w2g,
               const float* __restrict__ w3g,
               const float* __restrict__ w4g,
               float* __restrict__ out,
               int Btot)
{
    extern __shared__ char sm[];
    u32 smb;
    asm("{ .reg .u64 t; cvta.to.shared.u64 t, %1; cvt.u32.u64 %0, t; }"
        : "=r"(smb) : "l"(sm));

    const int tid  = threadIdx.x;
    const int w    = tid >> 5;
    const int lane = tid & 31;
    const int b0   = blockIdx.x * 64;

    // ---- stage weights: 3-way exact bf16 split + XOR swizzle ----
    for (int idx = tid; idx < 128 * 128; idx += THREADS) {
        int n = idx >> 7, k = idx & 127;
        float v = w2g[idx];
        float r1_ = v - bfv(v);
        float r2_ = r1_ - bfv(r1_);
        u32 off = (u32)(n * 256 + (((k >> 3) ^ (n & 7)) << 4) + (k & 7) * 2);
        *(__nv_bfloat16*)(sm + SW2 +     0 + off) = __float2bfloat16(v);
        *(__nv_bfloat16*)(sm + SW2 + 32768 + off) = __float2bfloat16(r1_);
        *(__nv_bfloat16*)(sm + SW2 + 65536 + off) = __float2bfloat16(r2_);
    }
    for (int idx = tid; idx < 64 * 128; idx += THREADS) {
        int n = idx >> 7, k = idx & 127;
        float v = w3g[idx];
        float r1_ = v - bfv(v);
        float r2_ = r1_ - bfv(r1_);
        u32 off = (u32)(n * 256 + (((k >> 3) ^ (n & 7)) << 4) + (k & 7) * 2);
        *(__nv_bfloat16*)(sm + SW3 +     0 + off) = __float2bfloat16(v);
        *(__nv_bfloat16*)(sm + SW3 + 16384 + off) = __float2bfloat16(r1_);
        *(__nv_bfloat16*)(sm + SW3 + 32768 + off) = __float2bfloat16(r2_);
    }
    for (int idx = tid; idx < 128 * 16; idx += THREADS) {
        int n = idx >> 4, k = idx & 15;
        float v = w1g[idx];
        float r1_ = v - bfv(v);
        float r2_ = r1_ - bfv(r1_);
        u32 off = (u32)(n * 32 + (((k >> 3) ^ (n & 1)) << 4) + (k & 7) * 2);
        *(__nv_bfloat16*)(sm + SW1 +    0 + off) = __float2bfloat16(v);
        *(__nv_bfloat16*)(sm + SW1 + 4096 + off) = __float2bfloat16(r1_);
        *(__nv_bfloat16*)(sm + SW1 + 8192 + off) = __float2bfloat16(r2_);
    }
    for (int idx = tid; idx < 16 * 64; idx += THREADS) {
        int n = idx >> 6, k = idx & 63;
        float v = (n < 10) ? w4g[n * 64 + k] : 0.0f;
        float r1_ = v - bfv(v);
        float r2_ = r1_ - bfv(r1_);
        u32 off = (u32)(n * 128 + (((k >> 3) ^ (n & 7)) << 4) + (k & 7) * 2);
        *(__nv_bfloat16*)(sm + SW4 +    0 + off) = __float2bfloat16(v);
        *(__nv_bfloat16*)(sm + SW4 + 2048 + off) = __float2bfloat16(r1_);
        *(__nv_bfloat16*)(sm + SW4 + 4096 + off) = __float2bfloat16(r2_);
    }

    // ---- lane roles ----
    const int arow = ((lane >> 3) & 1) * 8 + (lane & 7);
    const int ac   = lane >> 4;
    const int brow = ((lane >> 4) << 3) + (lane & 7);
    const int badd = (lane >> 3) & 1;
    const int r_   = lane >> 2;
    const int c_   = lane & 3;
    const u32 rx8  = (u32)(lane & 7) << 4;

    // ---- warp roles (16 warps) ----
    const int Nw  = w & 7;    // L1/L2: n16 block
    const int Mw  = w >> 3;   // L1/L2: m32 block
    const int Nw3 = w & 3;    // L3: n16 block
    const int Mw3 = w >> 2;   // L3: m16 block
    // L4: warps 0..3, m16 block = w

    // ---- x staging role ----
    const int bx = tid >> 3;
    const int fx = (tid & 7) * 2;
    const u32 xbase = smb + SXS + (u32)(bx * 32 + (((fx >> 3) ^ (bx & 1)) << 4) + (fx & 7) * 2);

    // ---- membranes ----
    float m1[16], m2[16], m3[8], m4[8];
#pragma unroll
    for (int i = 0; i < 16; i++) { m1[i] = 0.f; m2[i] = 0.f; }
#pragma unroll
    for (int i = 0; i < 8; i++) { m3[i] = 0.f; m4[i] = 0.f; }

    __syncthreads();

    // ---- hoist L1 B fragments (constant over t) ----
    u32 bw1[3][4];
#pragma unroll
    for (int lv = 0; lv < 3; lv++)
        ldsm4(bw1[lv], smb + SW1 + (u32)(lv * 4096 + (16 * Nw + brow) * 32)
                       + (((u32)badd << 4) ^ ((u32)(brow & 1) << 4)));

    auto stage_x0 = [&](int t) {
        float2 v = *(const float2*)(x + ((size_t)t * (size_t)Btot + (size_t)(b0 + bx)) * 16 + fx);
        float e0 = v.x - bfv(v.x), e1 = v.y - bfv(v.y);
        float f0 = e0 - bfv(e0),  f1 = e1 - bfv(e1);
        sts32(xbase,        bfb(v.x) | (bfb(v.y) << 16));
        sts32(xbase + 2048, bfb(e0) | (bfb(e1) << 16));
        sts32(xbase + 4096, bfb(f0) | (bfb(f1) << 16));
    };

    auto do_L1 = [&]() {
        float acc[4][4];
#pragma unroll
        for (int j = 0; j < 4; j++)
#pragma unroll
            for (int e = 0; e < 4; e++) acc[j][e] = 0.f;
        const int la[6] = {0, 0, 1, 0, 1, 2};
        const int lb[6] = {0, 1, 0, 2, 1, 0};
#pragma unroll
        for (int M = 0; M < 2; M++) {
            u32 ax[3][4];
#pragma unroll
            for (int lv = 0; lv < 3; lv++)
                ldsm4(ax[lv], smb + SXS + (u32)(lv * 2048 + (32 * Mw + 16 * M + arow) * 32)
                              + (((u32)ac << 4) ^ ((u32)(arow & 1) << 4)));
#pragma unroll
            for (int s = 0; s < 6; s++) {
                mma_bf16(acc[M * 2 + 0], ax[la[s]], bw1[lb[s]][0], bw1[lb[s]][1]);
                mma_bf16(acc[M * 2 + 1], ax[la[s]], bw1[lb[s]][2], bw1[lb[s]][3]);
            }
        }
#pragma unroll
        for (int M = 0; M < 2; M++)
#pragma unroll
            for (int nb = 0; nb < 2; nb++) {
                u32 p0, p1;
                lif4(&m1[(M * 2 + nb) * 4], acc[M * 2 + nb], p0, p1);
                u32 a0 = smb + SS1 + (u32)((32 * Mw + 16 * M + r_) * 256)
                         + (((u32)(2 * Nw + nb) << 4) ^ ((u32)r_ << 4)) + 4 * c_;
                sts32(a0, p0);
                sts32(a0 + 8 * 256, p1);
            }
    };

    // ===== prologue =====
    stage_x0(0);
    __syncthreads();
    do_L1();
    __syncthreads();

    for (int t = 0; t < T_STEPS; t++) {
        // ===== phase A: L2(t) + prefetch/stage x(t+1) =====
        {
            float2 xv = make_float2(0.f, 0.f);
            if (t + 1 < T_STEPS)
                xv = *(const float2*)(x + ((size_t)(t + 1) * (size_t)Btot + (size_t)(b0 + bx)) * 16 + fx);

            float acc[4][4];
#pragma unroll
            for (int j = 0; j < 4; j++)
#pragma unroll
                for (int e = 0; e < 4; e++) acc[j][e] = 0.f;
#pragma unroll
            for (int kc = 0; kc < 8; kc++) {
                u32 a_[2][4];
#pragma unroll
                for (int M = 0; M < 2; M++)
                    ldsm4(a_[M], smb + SS1 + (u32)((32 * Mw + 16 * M + arow) * 256)
                                 + (((u32)(2 * kc + ac) << 4) ^ rx8));
#pragma unroll
                for (int s = 0; s < 3; s++) {
                    u32 b_[4];
                    ldsm4(b_, smb + SW2 + (u32)(s * 32768 + (16 * Nw + brow) * 256)
                              + (((u32)(2 * kc + badd) << 4) ^ rx8));
#pragma unroll
                    for (int M = 0; M < 2; M++) {
                        mma_bf16(acc[M * 2 + 0], a_[M], b_[0], b_[1]);
                        mma_bf16(acc[M * 2 + 1], a_[M], b_[2], b_[3]);
                    }
                }
            }
#pragma unroll
            for (int M = 0; M < 2; M++)
#pragma unroll
                for (int nb = 0; nb < 2; nb++) {
                    u32 p0, p1;
                    lif4(&m2[(M * 2 + nb) * 4], acc[M * 2 + nb], p0, p1);
                    u32 a0 = smb + SS2 + (u32)((32 * Mw + 16 * M + r_) * 256)
                             + (((u32)(2 * Nw + nb) << 4) ^ ((u32)r_ << 4)) + 4 * c_;
                    sts32(a0, p0);
                    sts32(a0 + 8 * 256, p1);
                }

            if (t + 1 < T_STEPS) {
                float e0 = xv.x - bfv(xv.x), e1 = xv.y - bfv(xv.y);
                float f0 = e0 - bfv(e0),    f1 = e1 - bfv(e1);
                sts32(xbase,        bfb(xv.x) | (bfb(xv.y) << 16));
                sts32(xbase + 2048, bfb(e0) | (bfb(e1) << 16));
                sts32(xbase + 4096, bfb(f0) | (bfb(f1) << 16));
            }
        }
        __syncthreads();

        // ===== phase B: L3(t), warp M16 x N16 =====
        {
            float acc[2][4];
#pragma unroll
            for (int j = 0; j < 2; j++)
#pragma unroll
                for (int e = 0; e < 4; e++) acc[j][e] = 0.f;
#pragma unroll
            for (int kc = 0; kc < 8; kc++) {
                u32 a_[4];
                ldsm4(a_, smb + SS2 + (u32)((16 * Mw3 + arow) * 256)
                          + (((u32)(2 * kc + ac) << 4) ^ rx8));
#pragma unroll
                for (int s = 0; s < 3; s++) {
                    u32 b_[4];
                    ldsm4(b_, smb + SW3 + (u32)(s * 16384 + (16 * Nw3 + brow) * 256)
                              + (((u32)(2 * kc + badd) << 4) ^ rx8));
                    mma_bf16(acc[0], a_, b_[0], b_[1]);
                    mma_bf16(acc[1], a_, b_[2], b_[3]);
                }
            }
#pragma unroll
            for (int nb = 0; nb < 2; nb++) {
                u32 p0, p1;
                lif4(&m3[nb * 4], acc[nb], p0, p1);
                u32 a0 = smb + SS3 + (u32)((16 * Mw3 + r_) * 128)
                         + (((u32)(2 * Nw3 + nb) << 4) ^ ((u32)r_ << 4)) + 4 * c_;
                sts32(a0, p0);
                sts32(a0 + 8 * 128, p1);
            }
        }
        __syncthreads();

        // ===== phase C: L4(t) on warps 0..3 + L1(t+1) on all =====
        {
            if (w < 4) {
                float acc[2][4];
#pragma unroll
                for (int j = 0; j < 2; j++)
#pragma unroll
                    for (int e = 0; e < 4; e++) acc[j][e] = 0.f;
#pragma unroll
                for (int kc = 0; kc < 4; kc++) {
                    u32 a_[4];
                    ldsm4(a_, smb + SS3 + (u32)((16 * w + arow) * 128)
                              + (((u32)(2 * kc + ac) << 4) ^ rx8));
#pragma unroll
                    for (int s = 0; s < 3; s++) {
                        u32 b_[4];
                        ldsm4(b_, smb + SW4 + (u32)(s * 2048 + brow * 128)
                                  + (((u32)(2 * kc + badd) << 4) ^ rx8));
                        mma_bf16(acc[0], a_, b_[0], b_[1]);
                        mma_bf16(acc[1], a_, b_[2], b_[3]);
                    }
                }
                u32 q0, q1;
                lif4(&m4[0], acc[0], q0, q1);
                lif4(&m4[4], acc[1], q0, q1);
                float s4[8];
#pragma unroll
                for (int e = 0; e < 8; e++)
                    s4[e] = (m4[e] > THR) ? 1.0f : 0.0f;
                size_t row0 = (size_t)t * (size_t)Btot + (size_t)(b0 + 16 * w + r_);
                *(float2*)(out + row0 * 10 + 2 * c_)       = make_float2(s4[0], s4[1]);
                *(float2*)(out + (row0 + 8) * 10 + 2 * c_) = make_float2(s4[2], s4[3]);
                if (c_ == 0) {
                    *(float2*)(out + row0 * 10 + 8)       = make_float2(s4[4], s4[5]);
                    *(float2*)(out + (row0 + 8) * 10 + 8) = make_float2(s4[6], s4[7]);
                }
            }
            if (t + 1 < T_STEPS)
                do_L1();
        }
        __syncthreads();
    }
}

extern "C" void kernel_launch(void* const* d_in, const int* in_sizes, int n_in,
                              void* d_out, int out_size) {
    const float* x  = (const float*)d_in[0];
    const float* w1 = (const float*)d_in[1];
    const float* w2 = (const float*)d_in[2];
    const float* w3 = (const float*)d_in[3];
    const float* w4 = (const float*)d_in[4];
    float* out = (float*)d_out;

    const int Btot = in_sizes[0] / (T_STEPS * 16);  // 65536
    const int grid = Btot / 64;                     // 1024

    cudaFuncSetAttribute(snn_mma_kernel,
                         cudaFuncAttributeMaxDynamicSharedMemorySize,
                         SM_TOTAL);
    snn_mma_kernel<<<grid, THREADS, SM_TOTAL>>>(x, w1, w2, w3, w4, out, Btot);
}

// round 12
// speedup vs baseline: 1.1608x; 1.1608x over previous
#include <cuda_runtime.h>
#include <cuda_bf16.h>

#define THREADS 256
#define T_STEPS 20
#define BETA 0.9f
#define THR 1.0f

typedef unsigned int u32;

// ---- smem byte offsets (dedicated regions) ----
#define SW1 0            // 3 x 128 x 32B
#define SW2 12288        // 3 x 128 x 256B
#define SW3 110592       // 3 x 64 x 256B
#define SW4 159744       // 3 x 16 x 128B
#define SS1 165888       // 64 x 256B
#define SS2 182272       // 64 x 256B
#define SS3 198656       // 64 x 128B
#define SXS 206848       // 3 x 64 x 32B
#define SM_TOTAL 212992

__device__ __forceinline__ float bfv(float v) { return __bfloat162float(__float2bfloat16(v)); }
__device__ __forceinline__ u32 bfb(float v) { return (u32)__bfloat16_as_ushort(__float2bfloat16(v)); }

__device__ __forceinline__ void ldsm4(u32 a[4], u32 addr) {
    asm volatile("ldmatrix.sync.aligned.m8n8.x4.shared.b16 {%0,%1,%2,%3}, [%4];"
        : "=r"(a[0]), "=r"(a[1]), "=r"(a[2]), "=r"(a[3]) : "r"(addr));
}
__device__ __forceinline__ void ldsm2(u32 &r0, u32 &r1, u32 addr) {
    asm volatile("ldmatrix.sync.aligned.m8n8.x2.shared.b16 {%0,%1}, [%2];"
        : "=r"(r0), "=r"(r1) : "r"(addr));
}
__device__ __forceinline__ void mma_bf16(float d[4], const u32 a[4], u32 b0, u32 b1) {
    asm volatile("mma.sync.aligned.m16n8k16.row.col.f32.bf16.bf16.f32 "
        "{%0,%1,%2,%3}, {%4,%5,%6,%7}, {%8,%9}, {%0,%1,%2,%3};"
        : "+f"(d[0]), "+f"(d[1]), "+f"(d[2]), "+f"(d[3])
        : "r"(a[0]), "r"(a[1]), "r"(a[2]), "r"(a[3]), "r"(b0), "r"(b1));
}
__device__ __forceinline__ void sts32(u32 addr, u32 v) {
    asm volatile("st.shared.b32 [%0], %1;" :: "r"(addr), "r"(v) : "memory");
}

__device__ __forceinline__ void lif4(float* mem, const float* d, u32 &p0, u32 &p1) {
    float s[4];
#pragma unroll
    for (int e = 0; e < 4; e++) {
        float m = mem[e];
        float reset = (m > THR) ? 1.0f : 0.0f;
        m = fmaf(BETA, m, d[e]) - reset;
        mem[e] = m;
        s[e] = (m > THR) ? 1.0f : 0.0f;
    }
    p0 = (s[0] != 0.0f ? 0x3F80u : 0u) | (s[1] != 0.0f ? 0x3F800000u : 0u);
    p1 = (s[2] != 0.0f ? 0x3F80u : 0u) | (s[3] != 0.0f ? 0x3F800000u : 0u);
}

__global__ void __launch_bounds__(THREADS, 1)
snn_mma_kernel(const float* __restrict__ x,
               const float* __restrict__ w1g,
               const float* __restrict__ w2g,
               const float* __restrict__ w3g,
               const float* __restrict__ w4g,
               float* __restrict__ out,
               int Btot)
{
    extern __shared__ char sm[];
    u32 smb;
    asm("{ .reg .u64 t; cvta.to.shared.u64 t, %1; cvt.u32.u64 %0, t; }"
        : "=r"(smb) : "l"(sm));

    const int tid  = threadIdx.x;
    const int w    = tid >> 5;
    const int lane = tid & 31;
    const int b0   = blockIdx.x * 64;

    // ---- stage weights: 3-way exact bf16 split + XOR swizzle ----
    for (int idx = tid; idx < 128 * 128; idx += THREADS) {
        int n = idx >> 7, k = idx & 127;
        float v = w2g[idx];
        float r1_ = v - bfv(v);
        float r2_ = r1_ - bfv(r1_);
        u32 off = (u32)(n * 256 + (((k >> 3) ^ (n & 7)) << 4) + (k & 7) * 2);
        *(__nv_bfloat16*)(sm + SW2 +     0 + off) = __float2bfloat16(v);
        *(__nv_bfloat16*)(sm + SW2 + 32768 + off) = __float2bfloat16(r1_);
        *(__nv_bfloat16*)(sm + SW2 + 65536 + off) = __float2bfloat16(r2_);
    }
    for (int idx = tid; idx < 64 * 128; idx += THREADS) {
        int n = idx >> 7, k = idx & 127;
        float v = w3g[idx];
        float r1_ = v - bfv(v);
        float r2_ = r1_ - bfv(r1_);
        u32 off = (u32)(n * 256 + (((k >> 3) ^ (n & 7)) << 4) + (k & 7) * 2);
        *(__nv_bfloat16*)(sm + SW3 +     0 + off) = __float2bfloat16(v);
        *(__nv_bfloat16*)(sm + SW3 + 16384 + off) = __float2bfloat16(r1_);
        *(__nv_bfloat16*)(sm + SW3 + 32768 + off) = __float2bfloat16(r2_);
    }
    for (int idx = tid; idx < 128 * 16; idx += THREADS) {
        int n = idx >> 4, k = idx & 15;
        float v = w1g[idx];
        float r1_ = v - bfv(v);
        float r2_ = r1_ - bfv(r1_);
        u32 off = (u32)(n * 32 + (((k >> 3) ^ (n & 1)) << 4) + (k & 7) * 2);
        *(__nv_bfloat16*)(sm + SW1 +    0 + off) = __float2bfloat16(v);
        *(__nv_bfloat16*)(sm + SW1 + 4096 + off) = __float2bfloat16(r1_);
        *(__nv_bfloat16*)(sm + SW1 + 8192 + off) = __float2bfloat16(r2_);
    }
    for (int idx = tid; idx < 16 * 64; idx += THREADS) {
        int n = idx >> 6, k = idx & 63;
        float v = (n < 10) ? w4g[n * 64 + k] : 0.0f;
        float r1_ = v - bfv(v);
        float r2_ = r1_ - bfv(r1_);
        u32 off = (u32)(n * 128 + (((k >> 3) ^ (n & 7)) << 4) + (k & 7) * 2);
        *(__nv_bfloat16*)(sm + SW4 +    0 + off) = __float2bfloat16(v);
        *(__nv_bfloat16*)(sm + SW4 + 2048 + off) = __float2bfloat16(r1_);
        *(__nv_bfloat16*)(sm + SW4 + 4096 + off) = __float2bfloat16(r2_);
    }

    // ---- lane roles ----
    const int arow = ((lane >> 3) & 1) * 8 + (lane & 7);
    const int ac   = lane >> 4;
    const int brow = ((lane >> 4) << 3) + (lane & 7);
    const int badd = (lane >> 3) & 1;
    const int r_   = lane >> 2;
    const int c_   = lane & 3;
    const u32 rx8  = (u32)(lane & 7) << 4;

    // ---- membranes ----
    float m1[32], m2[32], m3[16], m4[4];
#pragma unroll
    for (int i = 0; i < 32; i++) { m1[i] = 0.f; m2[i] = 0.f; }
#pragma unroll
    for (int i = 0; i < 16; i++) m3[i] = 0.f;
#pragma unroll
    for (int i = 0; i < 4; i++)  m4[i] = 0.f;

    const int np3 = w & 3,  bh  = w >> 2;   // L3 role
    const int Mw  = w >> 1, nb4 = w & 1;    // L4 role

    // ---- x staging role ----
    const int bsx = tid >> 2;
    const int f4  = (tid & 3) << 2;
    const u32 xbase = smb + SXS + (u32)(bsx * 32 + (((f4 >> 3) ^ (bsx & 1)) << 4) + (f4 & 7) * 2);

    __syncthreads();

    // ---- hoist L1 B fragments (constant over t) ----
    u32 bw1[3][4];
#pragma unroll
    for (int lv = 0; lv < 3; lv++)
        ldsm4(bw1[lv], smb + SW1 + (u32)(lv * 4096 + (16 * w + brow) * 32)
                       + (((u32)badd << 4) ^ ((u32)(brow & 1) << 4)));

    auto stage_x = [&](int t) {
        float4 v = *(const float4*)(x + ((size_t)t * (size_t)Btot + (size_t)(b0 + bsx)) * 16 + f4);
        float e0 = v.x - bfv(v.x), e1 = v.y - bfv(v.y), e2 = v.z - bfv(v.z), e3 = v.w - bfv(v.w);
        float g0 = e0 - bfv(e0), g1 = e1 - bfv(e1), g2 = e2 - bfv(e2), g3 = e3 - bfv(e3);
        sts32(xbase,            bfb(v.x) | (bfb(v.y) << 16));
        sts32(xbase + 4,        bfb(v.z) | (bfb(v.w) << 16));
        sts32(xbase + 2048,     bfb(e0) | (bfb(e1) << 16));
        sts32(xbase + 2048 + 4, bfb(e2) | (bfb(e3) << 16));
        sts32(xbase + 4096,     bfb(g0) | (bfb(g1) << 16));
        sts32(xbase + 4096 + 4, bfb(g2) | (bfb(g3) << 16));
    };

    auto do_L1 = [&]() {   // L1: warp M64 x N16, K=16, 6 split terms -> s1
        float acc[32];
#pragma unroll
        for (int i = 0; i < 32; i++) acc[i] = 0.f;
        const int la[6] = {0, 0, 1, 0, 1, 2};
        const int lb[6] = {0, 1, 0, 2, 1, 0};
#pragma unroll
        for (int M = 0; M < 4; M++) {
            u32 ax[3][4];
#pragma unroll
            for (int lv = 0; lv < 3; lv++)
                ldsm4(ax[lv], smb + SXS + (u32)(lv * 2048 + (16 * M + arow) * 32)
                              + (((u32)ac << 4) ^ ((u32)(arow & 1) << 4)));
#pragma unroll
            for (int s = 0; s < 6; s++) {
                mma_bf16(&acc[(M * 2 + 0) * 4], ax[la[s]], bw1[lb[s]][0], bw1[lb[s]][1]);
                mma_bf16(&acc[(M * 2 + 1) * 4], ax[la[s]], bw1[lb[s]][2], bw1[lb[s]][3]);
            }
        }
#pragma unroll
        for (int M = 0; M < 4; M++)
#pragma unroll
            for (int nb = 0; nb < 2; nb++) {
                u32 p0, p1;
                lif4(&m1[(M * 2 + nb) * 4], &acc[(M * 2 + nb) * 4], p0, p1);
                u32 a0 = smb + SS1 + (u32)((16 * M + r_) * 256)
                         + (((u32)(2 * w + nb) << 4) ^ ((u32)r_ << 4)) + 4 * c_;
                sts32(a0, p0);
                sts32(a0 + 8 * 256, p1);
            }
    };

    auto do_L4 = [&](int tt) {   // L4(tt): warp (Mw, nb4), K=64 -> out
        float acc[4] = {0.f, 0.f, 0.f, 0.f};
#pragma unroll
        for (int kc = 0; kc < 4; kc++) {
            u32 a_[4];
            ldsm4(a_, smb + SS3 + (u32)((16 * Mw + arow) * 128)
                      + (((u32)(2 * kc + ac) << 4) ^ rx8));
#pragma unroll
            for (int s = 0; s < 3; s++) {
                u32 b0r, b1r;
                ldsm2(b0r, b1r, smb + SW4 + (u32)(s * 2048 + (8 * nb4 + (lane & 7)) * 128)
                              + (((u32)(2 * kc + badd) << 4) ^ ((u32)(lane & 7) << 4)));
                mma_bf16(acc, a_, b0r, b1r);
            }
        }
        float s4[4];
#pragma unroll
        for (int e = 0; e < 4; e++) {
            float m = m4[e];
            float reset = (m > THR) ? 1.0f : 0.0f;
            m = fmaf(BETA, m, acc[e]) - reset;
            m4[e] = m;
            s4[e] = (m > THR) ? 1.0f : 0.0f;
        }
        size_t row0 = (size_t)tt * (size_t)Btot + (size_t)(b0 + 16 * Mw + r_);
        if (nb4 == 0) {
            *(float2*)(out + row0 * 10 + 2 * c_)       = make_float2(s4[0], s4[1]);
            *(float2*)(out + (row0 + 8) * 10 + 2 * c_) = make_float2(s4[2], s4[3]);
        } else if (c_ == 0) {
            *(float2*)(out + row0 * 10 + 8)       = make_float2(s4[0], s4[1]);
            *(float2*)(out + (row0 + 8) * 10 + 8) = make_float2(s4[2], s4[3]);
        }
    };

    // ===== prologue: stage x(0); L1(0) =====
    stage_x(0);
    __syncthreads();
    do_L1();
    __syncthreads();

    for (int t = 0; t < T_STEPS; t++) {
        // ===== phase A: L4(t-1) + L2(t) + stage x(t+1) =====
        {
            float4 xv;
            if (t + 1 < T_STEPS)
                xv = *(const float4*)(x + ((size_t)(t + 1) * (size_t)Btot + (size_t)(b0 + bsx)) * 16 + f4);

            if (t > 0)
                do_L4(t - 1);

            float acc[32];
#pragma unroll
            for (int i = 0; i < 32; i++) acc[i] = 0.f;
#pragma unroll
            for (int kc = 0; kc < 8; kc++) {
                u32 a_[4][4];
#pragma unroll
                for (int M = 0; M < 4; M++)
                    ldsm4(a_[M], smb + SS1 + (u32)((16 * M + arow) * 256)
                                 + (((u32)(2 * kc + ac) << 4) ^ rx8));
#pragma unroll
                for (int s = 0; s < 3; s++) {
                    u32 b_[4];
                    ldsm4(b_, smb + SW2 + (u32)(s * 32768 + (16 * w + brow) * 256)
                              + (((u32)(2 * kc + badd) << 4) ^ rx8));
#pragma unroll
                    for (int M = 0; M < 4; M++) {
                        mma_bf16(&acc[(M * 2 + 0) * 4], a_[M], b_[0], b_[1]);
                        mma_bf16(&acc[(M * 2 + 1) * 4], a_[M], b_[2], b_[3]);
                    }
                }
            }
#pragma unroll
            for (int M = 0; M < 4; M++)
#pragma unroll
                for (int nb = 0; nb < 2; nb++) {
                    u32 p0, p1;
                    lif4(&m2[(M * 2 + nb) * 4], &acc[(M * 2 + nb) * 4], p0, p1);
                    u32 a0 = smb + SS2 + (u32)((16 * M + r_) * 256)
                             + (((u32)(2 * w + nb) << 4) ^ ((u32)r_ << 4)) + 4 * c_;
                    sts32(a0, p0);
                    sts32(a0 + 8 * 256, p1);
                }

            if (t + 1 < T_STEPS) {
                float e0 = xv.x - bfv(xv.x), e1 = xv.y - bfv(xv.y), e2 = xv.z - bfv(xv.z), e3 = xv.w - bfv(xv.w);
                float g0 = e0 - bfv(e0), g1 = e1 - bfv(e1), g2 = e2 - bfv(e2), g3 = e3 - bfv(e3);
                sts32(xbase,            bfb(xv.x) | (bfb(xv.y) << 16));
                sts32(xbase + 4,        bfb(xv.z) | (bfb(xv.w) << 16));
                sts32(xbase + 2048,     bfb(e0) | (bfb(e1) << 16));
                sts32(xbase + 2048 + 4, bfb(e2) | (bfb(e3) << 16));
                sts32(xbase + 4096,     bfb(g0) | (bfb(g1) << 16));
                sts32(xbase + 4096 + 4, bfb(g2) | (bfb(g3) << 16));
            }
        }
        __syncthreads();

        // ===== phase B: L3(t) + L1(t+1) =====
        {
            float acc[16];
#pragma unroll
            for (int i = 0; i < 16; i++) acc[i] = 0.f;
#pragma unroll
            for (int kc = 0; kc < 8; kc++) {
                u32 a_[2][4];
#pragma unroll
                for (int M = 0; M < 2; M++)
                    ldsm4(a_[M], smb + SS2 + (u32)((32 * bh + 16 * M + arow) * 256)
                                 + (((u32)(2 * kc + ac) << 4) ^ rx8));
#pragma unroll
                for (int s = 0; s < 3; s++) {
                    u32 b_[4];
                    ldsm4(b_, smb + SW3 + (u32)(s * 16384 + (16 * np3 + brow) * 256)
                              + (((u32)(2 * kc + badd) << 4) ^ rx8));
#pragma unroll
                    for (int M = 0; M < 2; M++) {
                        mma_bf16(&acc[(M * 2 + 0) * 4], a_[M], b_[0], b_[1]);
                        mma_bf16(&acc[(M * 2 + 1) * 4], a_[M], b_[2], b_[3]);
                    }
                }
            }
#pragma unroll
            for (int M = 0; M < 2; M++)
#pragma unroll
                for (int nb = 0; nb < 2; nb++) {
                    u32 p0, p1;
                    lif4(&m3[(M * 2 + nb) * 4], &acc[(M * 2 + nb) * 4], p0, p1);
                    u32 a0 = smb + SS3 + (u32)((32 * bh + 16 * M + r_) * 128)
                             + (((u32)(2 * np3 + nb) << 4) ^ ((u32)r_ << 4)) + 4 * c_;
                    sts32(a0, p0);
                    sts32(a0 + 8 * 128, p1);
                }

            if (t + 1 < T_STEPS)
                do_L1();
        }
        __syncthreads();
    }

    // ===== epilogue: L4(T-1) =====
    do_L4(T_STEPS - 1);
}

extern "C" void kernel_launch(void* const* d_in, const int* in_sizes, int n_in,
                              void* d_out, int out_size) {
    const float* x  = (const float*)d_in[0];
    const float* w1 = (const float*)d_in[1];
    const float* w2 = (const float*)d_in[2];
    const float* w3 = (const float*)d_in[3];
    const float* w4 = (const float*)d_in[4];
    float* out = (float*)d_out;

    const int Btot = in_sizes[0] / (T_STEPS * 16);  // 65536
    const int grid = Btot / 64;                     // 1024

    cudaFuncSetAttribute(snn_mma_kernel,
                         cudaFuncAttributeMaxDynamicSharedMemorySize,
                         SM_TOTAL);
    snn_mma_kernel<<<grid, THREADS, SM_TOTAL>>>(x, w1, w2, w3, w4, out, Btot);
}

// round 13
// speedup vs baseline: 1.1634x; 1.0023x over previous
#include <cuda_runtime.h>
#include <cuda_bf16.h>

#define THREADS 128
#define T_STEPS 20
#define BETA 0.9f
#define THR 1.0f

typedef unsigned int u32;
typedef unsigned long long u64;

// ---- weight fragments in device globals (filled by prep kernel) ----
__device__ u64 gW2f[3 * 16 * 8 * 32];   // [s][nb16][kc8][lane]
__device__ u64 gW3f[3 * 8 * 8 * 32];    // [s][nb8][kc8][lane]
__device__ u64 gW1f[3 * 16 * 32];       // [s][nb16][lane]  (kc=0 only)
__device__ u64 gW4f[3 * 2 * 4 * 32];    // [s][nb2][kc4][lane]

// ---- smem byte offsets (spike/x buffers only) ----
#define SS1 0        // 32 x 256B
#define SS2 8192     // 32 x 256B
#define SS3 16384    // 32 x 128B
#define SXS 20480    // 3 x 32 x 32B
#define SM_TOTAL 23552

__device__ __forceinline__ float bfv(float v) { return __bfloat162float(__float2bfloat16(v)); }
__device__ __forceinline__ u32 bfb(float v) { return (u32)__bfloat16_as_ushort(__float2bfloat16(v)); }

__device__ __forceinline__ float split_lvl(float v, int s) {
    float s0 = bfv(v);
    if (s == 0) return s0;
    float r = v - s0;
    float s1 = bfv(r);
    if (s == 1) return s1;
    return bfv(r - s1);
}

__global__ void prep_kernel(const float* __restrict__ w1g, const float* __restrict__ w2g,
                            const float* __restrict__ w3g, const float* __restrict__ w4g)
{
    int idx = blockIdx.x * blockDim.x + threadIdx.x;
    int lane = idx & 31;
    int nrow = lane >> 2;          // n offset within n8 block
    int koff = (lane & 3) * 2;     // k offset within k8 chunk
    if (idx < 12288) {             // W2: [3][16][8][32]
        int f = idx >> 5; int kc = f & 7; int nb = (f >> 3) & 15; int s = f >> 7;
        int n = nb * 8 + nrow; int k = kc * 16 + koff;
        u32 lo = bfb(split_lvl(w2g[n * 128 + k], s))     | (bfb(split_lvl(w2g[n * 128 + k + 1], s)) << 16);
        u32 hi = bfb(split_lvl(w2g[n * 128 + k + 8], s)) | (bfb(split_lvl(w2g[n * 128 + k + 9], s)) << 16);
        gW2f[idx] = (u64)lo | ((u64)hi << 32);
    } else if (idx < 18432) {      // W3: [3][8][8][32]
        int j = idx - 12288; int f = j >> 5; int kc = f & 7; int nb = (f >> 3) & 7; int s = f >> 6;
        int n = nb * 8 + nrow; int k = kc * 16 + koff;
        u32 lo = bfb(split_lvl(w3g[n * 128 + k], s))     | (bfb(split_lvl(w3g[n * 128 + k + 1], s)) << 16);
        u32 hi = bfb(split_lvl(w3g[n * 128 + k + 8], s)) | (bfb(split_lvl(w3g[n * 128 + k + 9], s)) << 16);
        gW3f[j] = (u64)lo | ((u64)hi << 32);
    } else if (idx < 19968) {      // W1: [3][16][32], K=16
        int j = idx - 18432; int f = j >> 5; int nb = f & 15; int s = f >> 4;
        int n = nb * 8 + nrow; int k = koff;
        u32 lo = bfb(split_lvl(w1g[n * 16 + k], s))     | (bfb(split_lvl(w1g[n * 16 + k + 1], s)) << 16);
        u32 hi = bfb(split_lvl(w1g[n * 16 + k + 8], s)) | (bfb(split_lvl(w1g[n * 16 + k + 9], s)) << 16);
        gW1f[j] = (u64)lo | ((u64)hi << 32);
    } else if (idx < 20736) {      // W4: [3][2][4][32], K=64, N padded to 16
        int j = idx - 19968; int f = j >> 5; int kc = f & 3; int nb = (f >> 2) & 1; int s = f >> 3;
        int n = nb * 8 + nrow; int k = kc * 16 + koff;
        float a0 = (n < 10) ? w4g[n * 64 + k]     : 0.f;
        float a1 = (n < 10) ? w4g[n * 64 + k + 1] : 0.f;
        float a2 = (n < 10) ? w4g[n * 64 + k + 8] : 0.f;
        float a3 = (n < 10) ? w4g[n * 64 + k + 9] : 0.f;
        u32 lo = bfb(split_lvl(a0, s)) | (bfb(split_lvl(a1, s)) << 16);
        u32 hi = bfb(split_lvl(a2, s)) | (bfb(split_lvl(a3, s)) << 16);
        gW4f[j] = (u64)lo | ((u64)hi << 32);
    }
}

__device__ __forceinline__ void ldsm4(u32 a[4], u32 addr) {
    asm volatile("ldmatrix.sync.aligned.m8n8.x4.shared.b16 {%0,%1,%2,%3}, [%4];"
        : "=r"(a[0]), "=r"(a[1]), "=r"(a[2]), "=r"(a[3]) : "r"(addr));
}
__device__ __forceinline__ void mma_bf16(float d[4], const u32 a[4], u32 b0, u32 b1) {
    asm volatile("mma.sync.aligned.m16n8k16.row.col.f32.bf16.bf16.f32 "
        "{%0,%1,%2,%3}, {%4,%5,%6,%7}, {%8,%9}, {%0,%1,%2,%3};"
        : "+f"(d[0]), "+f"(d[1]), "+f"(d[2]), "+f"(d[3])
        : "r"(a[0]), "r"(a[1]), "r"(a[2]), "r"(a[3]), "r"(b0), "r"(b1));
}
__device__ __forceinline__ void sts32(u32 addr, u32 v) {
    asm volatile("st.shared.b32 [%0], %1;" :: "r"(addr), "r"(v) : "memory");
}

__device__ __forceinline__ void lif4(float* mem, const float* d, u32 &p0, u32 &p1) {
    float s[4];
#pragma unroll
    for (int e = 0; e < 4; e++) {
        float m = mem[e];
        float reset = (m > THR) ? 1.0f : 0.0f;
        m = fmaf(BETA, m, d[e]) - reset;
        mem[e] = m;
        s[e] = (m > THR) ? 1.0f : 0.0f;
    }
    p0 = (s[0] != 0.0f ? 0x3F80u : 0u) | (s[1] != 0.0f ? 0x3F800000u : 0u);
    p1 = (s[2] != 0.0f ? 0x3F80u : 0u) | (s[3] != 0.0f ? 0x3F800000u : 0u);
}

__global__ void __launch_bounds__(THREADS, 2)
snn_mma_kernel(const float* __restrict__ x,
               float* __restrict__ out,
               int Btot)
{
    __shared__ __align__(16) char sm[SM_TOTAL];
    u32 smb;
    asm("{ .reg .u64 t; cvta.to.shared.u64 t, %1; cvt.u32.u64 %0, t; }"
        : "=r"(smb) : "l"(sm));

    const int tid  = threadIdx.x;
    const int w    = tid >> 5;     // 4 warps
    const int lane = tid & 31;
    const int b0   = blockIdx.x * 32;

    // ---- lane roles ----
    const int arow = ((lane >> 3) & 1) * 8 + (lane & 7);
    const int ac   = lane >> 4;
    const int r_   = lane >> 2;
    const int c_   = lane & 3;
    const u32 rx8  = (u32)(lane & 7) << 4;

    // ---- warp roles ----
    // L1/L2: warp n32 block = w (n = 32w .. 32w+31), M = 32 (all batches)
    // L3: warp n16 block = w
    // L4: Mw = w>>1 (m16 block), nb4 = w&1 (n8 block)
    const int Mw  = w >> 1, nb4 = w & 1;

    // ---- fragment pointers (per-lane) ----
    const u64* pW2 = gW2f + lane;
    const u64* pW3 = gW3f + lane;
    const u64* pW4 = gW4f + lane;

    // ---- hoist L1 B fragments (constant over t): 3 lv x 4 n8 ----
    u32 bw1[3][4][2];
#pragma unroll
    for (int lv = 0; lv < 3; lv++)
#pragma unroll
        for (int j = 0; j < 4; j++) {
            u64 q = gW1f[(lv * 16 + (w * 4 + j)) * 32 + lane];
            bw1[lv][j][0] = (u32)q;
            bw1[lv][j][1] = (u32)(q >> 32);
        }

    // ---- membranes ----
    float m1[32], m2[32], m3[16], m4[4];
#pragma unroll
    for (int i = 0; i < 32; i++) { m1[i] = 0.f; m2[i] = 0.f; }
#pragma unroll
    for (int i = 0; i < 16; i++) m3[i] = 0.f;
#pragma unroll
    for (int i = 0; i < 4; i++)  m4[i] = 0.f;

    // ---- x staging role: thread owns (batch bsx, feats f4..f4+3) ----
    const int bsx = tid >> 2;
    const int f4  = (tid & 3) << 2;
    const u32 xbase = smb + SXS + (u32)(bsx * 32 + (((f4 >> 3) ^ (bsx & 1)) << 4) + (f4 & 7) * 2);

    auto stage_x = [&](const float4& v) {
        float e0 = v.x - bfv(v.x), e1 = v.y - bfv(v.y), e2 = v.z - bfv(v.z), e3 = v.w - bfv(v.w);
        float g0 = e0 - bfv(e0), g1 = e1 - bfv(e1), g2 = e2 - bfv(e2), g3 = e3 - bfv(e3);
        sts32(xbase,            bfb(v.x) | (bfb(v.y) << 16));
        sts32(xbase + 4,        bfb(v.z) | (bfb(v.w) << 16));
        sts32(xbase + 1024,     bfb(e0) | (bfb(e1) << 16));
        sts32(xbase + 1024 + 4, bfb(e2) | (bfb(e3) << 16));
        sts32(xbase + 2048,     bfb(g0) | (bfb(g1) << 16));
        sts32(xbase + 2048 + 4, bfb(g2) | (bfb(g3) << 16));
    };

    auto do_L1 = [&]() {   // warp M32 x N32, K=16, 6 split terms -> s1
        float acc[32];
#pragma unroll
        for (int i = 0; i < 32; i++) acc[i] = 0.f;
        const int la[6] = {0, 0, 1, 0, 1, 2};
        const int lb[6] = {0, 1, 0, 2, 1, 0};
#pragma unroll
        for (int M = 0; M < 2; M++) {
            u32 ax[3][4];
#pragma unroll
            for (int lv = 0; lv < 3; lv++)
                ldsm4(ax[lv], smb + SXS + (u32)(lv * 1024 + (16 * M + arow) * 32)
                              + (((u32)ac << 4) ^ ((u32)(arow & 1) << 4)));
#pragma unroll
            for (int s = 0; s < 6; s++)
#pragma unroll
                for (int j = 0; j < 4; j++)
                    mma_bf16(&acc[(M * 4 + j) * 4], ax[la[s]], bw1[lb[s]][j][0], bw1[lb[s]][j][1]);
        }
#pragma unroll
        for (int M = 0; M < 2; M++)
#pragma unroll
            for (int j = 0; j < 4; j++) {
                u32 p0, p1;
                lif4(&m1[(M * 4 + j) * 4], &acc[(M * 4 + j) * 4], p0, p1);
                u32 a0 = smb + SS1 + (u32)((16 * M + r_) * 256)
                         + (((u32)(4 * w + j) << 4) ^ ((u32)r_ << 4)) + 4 * c_;
                sts32(a0, p0);
                sts32(a0 + 2048, p1);
            }
    };

    auto do_L4 = [&](int tt) {   // warp (Mw, nb4): M16 x N8, K=64
        float acc[4] = {0.f, 0.f, 0.f, 0.f};
#pragma unroll
        for (int kc = 0; kc < 4; kc++) {
            u32 a_[4];
            ldsm4(a_, smb + SS3 + (u32)((16 * Mw + arow) * 128)
                      + (((u32)(2 * kc + ac) << 4) ^ rx8));
#pragma unroll
            for (int s = 0; s < 3; s++) {
                u64 q = pW4[((s * 2 + nb4) * 4 + kc) * 32];
                mma_bf16(acc, a_, (u32)q, (u32)(q >> 32));
            }
        }
        float s4[4];
#pragma unroll
        for (int e = 0; e < 4; e++) {
            float m = m4[e];
            float reset = (m > THR) ? 1.0f : 0.0f;
            m = fmaf(BETA, m, acc[e]) - reset;
            m4[e] = m;
            s4[e] = (m > THR) ? 1.0f : 0.0f;
        }
        size_t row0 = (size_t)tt * (size_t)Btot + (size_t)(b0 + 16 * Mw + r_);
        if (nb4 == 0) {
            *(float2*)(out + row0 * 10 + 2 * c_)       = make_float2(s4[0], s4[1]);
            *(float2*)(out + (row0 + 8) * 10 + 2 * c_) = make_float2(s4[2], s4[3]);
        } else if (c_ == 0) {
            *(float2*)(out + row0 * 10 + 8)       = make_float2(s4[0], s4[1]);
            *(float2*)(out + (row0 + 8) * 10 + 8) = make_float2(s4[2], s4[3]);
        }
    };

    // ===== prologue: stage x(0); L1(0) =====
    {
        float4 v = *(const float4*)(x + ((size_t)0 * (size_t)Btot + (size_t)(b0 + bsx)) * 16 + f4);
        stage_x(v);
    }
    __syncthreads();
    do_L1();
    __syncthreads();

    for (int t = 0; t < T_STEPS; t++) {
        // ===== phase A: L4(t-1) + L2(t) + stage x(t+1) =====
        {
            float4 xv;
            if (t + 1 < T_STEPS)
                xv = *(const float4*)(x + ((size_t)(t + 1) * (size_t)Btot + (size_t)(b0 + bsx)) * 16 + f4);

            if (t > 0)
                do_L4(t - 1);

            // L2: warp M32 x N32, K=128, 3 splits
            float acc[32];
#pragma unroll
            for (int i = 0; i < 32; i++) acc[i] = 0.f;
#pragma unroll
            for (int kc = 0; kc < 8; kc++) {
                u32 a_[2][4];
#pragma unroll
                for (int M = 0; M < 2; M++)
                    ldsm4(a_[M], smb + SS1 + (u32)((16 * M + arow) * 256)
                                 + (((u32)(2 * kc + ac) << 4) ^ rx8));
#pragma unroll
                for (int s = 0; s < 3; s++) {
                    u64 q[4];
#pragma unroll
                    for (int j = 0; j < 4; j++)
                        q[j] = pW2[((s * 16 + (w * 4 + j)) * 8 + kc) * 32];
#pragma unroll
                    for (int M = 0; M < 2; M++)
#pragma unroll
                        for (int j = 0; j < 4; j++)
                            mma_bf16(&acc[(M * 4 + j) * 4], a_[M], (u32)q[j], (u32)(q[j] >> 32));
                }
            }
#pragma unroll
            for (int M = 0; M < 2; M++)
#pragma unroll
                for (int j = 0; j < 4; j++) {
                    u32 p0, p1;
                    lif4(&m2[(M * 4 + j) * 4], &acc[(M * 4 + j) * 4], p0, p1);
                    u32 a0 = smb + SS2 + (u32)((16 * M + r_) * 256)
                             + (((u32)(4 * w + j) << 4) ^ ((u32)r_ << 4)) + 4 * c_;
                    sts32(a0, p0);
                    sts32(a0 + 2048, p1);
                }

            if (t + 1 < T_STEPS)
                stage_x(xv);
        }
        __syncthreads();

        // ===== phase B: L3(t) + L1(t+1) =====
        {
            // L3: warp M32 x N16 (n16 block = w), K=128, 3 splits
            float acc[16];
#pragma unroll
            for (int i = 0; i < 16; i++) acc[i] = 0.f;
#pragma unroll
            for (int kc = 0; kc < 8; kc++) {
                u32 a_[2][4];
#pragma unroll
                for (int M = 0; M < 2; M++)
                    ldsm4(a_[M], smb + SS2 + (u32)((16 * M + arow) * 256)
                                 + (((u32)(2 * kc + ac) << 4) ^ rx8));
#pragma unroll
                for (int s = 0; s < 3; s++) {
                    u64 q0 = pW3[((s * 8 + (w * 2 + 0)) * 8 + kc) * 32];
                    u64 q1 = pW3[((s * 8 + (w * 2 + 1)) * 8 + kc) * 32];
#pragma unroll
                    for (int M = 0; M < 2; M++) {
                        mma_bf16(&acc[(M * 2 + 0) * 4], a_[M], (u32)q0, (u32)(q0 >> 32));
                        mma_bf16(&acc[(M * 2 + 1) * 4], a_[M], (u32)q1, (u32)(q1 >> 32));
                    }
                }
            }
#pragma unroll
            for (int M = 0; M < 2; M++)
#pragma unroll
                for (int nb = 0; nb < 2; nb++) {
                    u32 p0, p1;
                    lif4(&m3[(M * 2 + nb) * 4], &acc[(M * 2 + nb) * 4], p0, p1);
                    u32 a0 = smb + SS3 + (u32)((16 * M + r_) * 128)
                             + (((u32)(2 * w + nb) << 4) ^ ((u32)r_ << 4)) + 4 * c_;
                    sts32(a0, p0);
                    sts32(a0 + 1024, p1);
                }

            if (t + 1 < T_STEPS)
                do_L1();
        }
        __syncthreads();
    }

    // ===== epilogue: L4(T-1) =====
    do_L4(T_STEPS - 1);
}

extern "C" void kernel_launch(void* const* d_in, const int* in_sizes, int n_in,
                              void* d_out, int out_size) {
    const float* x  = (const float*)d_in[0];
    const float* w1 = (const float*)d_in[1];
    const float* w2 = (const float*)d_in[2];
    const float* w3 = (const float*)d_in[3];
    const float* w4 = (const float*)d_in[4];
    float* out = (float*)d_out;

    const int Btot = in_sizes[0] / (T_STEPS * 16);  // 65536

    prep_kernel<<<(20736 + 127) / 128, 128>>>(w1, w2, w3, w4);

    const int grid = Btot / 32;                     // 2048
    snn_mma_kernel<<<grid, THREADS>>>(x, out, Btot);
}